// round 1
// baseline (speedup 1.0000x reference)
#include <cuda_runtime.h>
#include <math.h>

// Problem constants
#define S_LEN 2048
#define HDIM  1024
#define NH    16
#define HD    64
#define E_NUM 8
#define F_DIM 2048

// ---------------- scratch (device globals; no allocations allowed) ----------
__device__ float g_hn  [S_LEN * HDIM];            // ln1 output
__device__ float g_qkv [S_LEN * 3 * HDIM];        // qkv projection
__device__ float g_attn[S_LEN * HDIM];            // attention output (pre out-proj)
__device__ float g_hn2 [S_LEN * HDIM];            // ln2 output
__device__ float g_hmid[(size_t)E_NUM * S_LEN * F_DIM];   // gated+gelu hidden (segmented by expert)
__device__ float g_ypair[(size_t)E_NUM * S_LEN * HDIM];   // per (token,expert) output rows
__device__ int   g_cnt [E_NUM];
__device__ int   g_list[E_NUM * S_LEN];
__device__ float g_gate[E_NUM * S_LEN];
__device__ int   g_slots[S_LEN * 2];

// ---------------- layernorm: one block per row -------------------------------
__global__ __launch_bounds__(256)
void ln_kernel(const float* __restrict__ x, const float* __restrict__ w,
               const float* __restrict__ b, float* __restrict__ out)
{
    int t = blockIdx.x;
    const float* xr = x + (size_t)t * HDIM;
    float v[4];
    float s = 0.f, s2 = 0.f;
#pragma unroll
    for (int i = 0; i < 4; i++) {
        v[i] = xr[threadIdx.x + (i << 8)];
        s += v[i]; s2 += v[i] * v[i];
    }
#pragma unroll
    for (int o = 16; o > 0; o >>= 1) {
        s  += __shfl_xor_sync(0xffffffffu, s,  o);
        s2 += __shfl_xor_sync(0xffffffffu, s2, o);
    }
    __shared__ float red[2][8];
    int wid = threadIdx.x >> 5, lane = threadIdx.x & 31;
    if (lane == 0) { red[0][wid] = s; red[1][wid] = s2; }
    __syncthreads();
    float ts = 0.f, ts2 = 0.f;
#pragma unroll
    for (int i = 0; i < 8; i++) { ts += red[0][i]; ts2 += red[1][i]; }
    float mu   = ts * (1.f / HDIM);
    float var  = ts2 * (1.f / HDIM) - mu * mu;
    float rstd = rsqrtf(var + 1e-5f);
    float* orow = out + (size_t)t * HDIM;
#pragma unroll
    for (int i = 0; i < 4; i++) {
        int hh = threadIdx.x + (i << 8);
        orow[hh] = (v[i] - mu) * rstd * w[hh] + b[hh];
    }
}

// ---------------- GEMM NT: C[M,N] = A[M,K] @ B[N,K]^T (+bias)(+res) ----------
// 64x64 tile, BK=16, 256 threads, 4x4 per thread. M,N mult of 64, K mult of 16.
__global__ __launch_bounds__(256)
void gemm_nt(const float* __restrict__ A, const float* __restrict__ B,
             const float* __restrict__ bias, const float* __restrict__ res,
             float* __restrict__ C, int M, int N, int K)
{
    __shared__ float As[16][68];
    __shared__ float Bs[16][68];
    int m0 = blockIdx.x << 6, n0 = blockIdx.y << 6;
    int tid = threadIdx.x;
    int ty = tid >> 4, tx = tid & 15;
    int lrow = tid >> 2, lk4 = (tid & 3) << 2;
    const float* Ap = A + (size_t)(m0 + lrow) * K + lk4;
    const float* Bp = B + (size_t)(n0 + lrow) * K + lk4;
    float acc[4][4] = {};
    for (int k0 = 0; k0 < K; k0 += 16) {
        float4 a = *(const float4*)(Ap + k0);
        float4 b = *(const float4*)(Bp + k0);
        As[lk4 + 0][lrow] = a.x; As[lk4 + 1][lrow] = a.y;
        As[lk4 + 2][lrow] = a.z; As[lk4 + 3][lrow] = a.w;
        Bs[lk4 + 0][lrow] = b.x; Bs[lk4 + 1][lrow] = b.y;
        Bs[lk4 + 2][lrow] = b.z; Bs[lk4 + 3][lrow] = b.w;
        __syncthreads();
#pragma unroll
        for (int kk = 0; kk < 16; kk++) {
            float4 av = *(const float4*)&As[kk][ty << 2];
            float4 bv = *(const float4*)&Bs[kk][tx << 2];
            float aa[4] = {av.x, av.y, av.z, av.w};
            float bb[4] = {bv.x, bv.y, bv.z, bv.w};
#pragma unroll
            for (int i = 0; i < 4; i++)
#pragma unroll
                for (int j = 0; j < 4; j++) acc[i][j] += aa[i] * bb[j];
        }
        __syncthreads();
    }
#pragma unroll
    for (int i = 0; i < 4; i++) {
        int m = m0 + (ty << 2) + i;
#pragma unroll
        for (int j = 0; j < 4; j++) {
            int n = n0 + (tx << 2) + j;
            float v = acc[i][j];
            if (bias) v += bias[n];
            if (res)  v += res[(size_t)m * N + n];
            C[(size_t)m * N + n] = v;
        }
    }
}

// ---------------- flash attention: block = (64 queries, 1 head) --------------
__global__ __launch_bounds__(256)
void attn_kernel(const float* __restrict__ qkv, float* __restrict__ outp)
{
    __shared__ float Qs [64][68];   // [query][dim], pre-scaled by 1/8
    __shared__ float Kst[64][36];   // [dim][key]
    __shared__ float Vs [32][68];   // [key][dim]
    __shared__ float Ps [64][36];   // [query][key]
    int q0 = blockIdx.x << 6;
    int h  = blockIdx.y;
    int tid = threadIdx.x, ty = tid >> 4, tx = tid & 15;

    // load Q tile (64x64), scale by 1/sqrt(64)
#pragma unroll
    for (int r = 0; r < 4; r++) {
        int s = tid + (r << 8);
        int row = s >> 4, c4 = (s & 15) << 2;
        float4 q = *(const float4*)&qkv[(size_t)(q0 + row) * 3072 + h * 64 + c4];
        Qs[row][c4 + 0] = q.x * 0.125f; Qs[row][c4 + 1] = q.y * 0.125f;
        Qs[row][c4 + 2] = q.z * 0.125f; Qs[row][c4 + 3] = q.w * 0.125f;
    }

    float O[4][4] = {};
    float mrow[4], lsum[4];
#pragma unroll
    for (int i = 0; i < 4; i++) { mrow[i] = -1e30f; lsum[i] = 0.f; }

    int ntiles = (q0 >> 5) + 2;
    for (int jt = 0; jt < ntiles; jt++) {
        int k0 = jt << 5;
        __syncthreads();   // prior PV done (and Q tile visible on first iter)
        // load K (transposed into [dim][key]) and V ([key][dim]) tiles: 32 keys
#pragma unroll
        for (int r = 0; r < 2; r++) {
            int s = tid + (r << 8);
            int row = s >> 4, c4 = (s & 15) << 2;
            const float* base = &qkv[(size_t)(k0 + row) * 3072 + h * 64 + c4];
            float4 kv = *(const float4*)(base + 1024);
            Kst[c4 + 0][row] = kv.x; Kst[c4 + 1][row] = kv.y;
            Kst[c4 + 2][row] = kv.z; Kst[c4 + 3][row] = kv.w;
            float4 vv = *(const float4*)(base + 2048);
            *(float4*)&Vs[row][c4] = vv;
        }
        __syncthreads();

        // S = Q K^T : rows 4ty..+3, cols 2tx..+1
        float sv[4][2];
#pragma unroll
        for (int i = 0; i < 4; i++) { sv[i][0] = 0.f; sv[i][1] = 0.f; }
#pragma unroll 8
        for (int kk = 0; kk < 64; kk++) {
            float b0 = Kst[kk][2 * tx], b1 = Kst[kk][2 * tx + 1];
#pragma unroll
            for (int i = 0; i < 4; i++) {
                float a = Qs[(ty << 2) + i][kk];
                sv[i][0] += a * b0; sv[i][1] += a * b1;
            }
        }
        // causal mask + online softmax
#pragma unroll
        for (int i = 0; i < 4; i++) {
            int qrow = q0 + (ty << 2) + i;
            float s0 = (k0 + 2 * tx     <= qrow) ? sv[i][0] : -1e30f;
            float s1 = (k0 + 2 * tx + 1 <= qrow) ? sv[i][1] : -1e30f;
            float rm = fmaxf(s0, s1);
#pragma unroll
            for (int o = 8; o > 0; o >>= 1)
                rm = fmaxf(rm, __shfl_xor_sync(0xffffffffu, rm, o));
            float mn = fmaxf(mrow[i], rm);
            float p0 = __expf(s0 - mn), p1 = __expf(s1 - mn);
            float rs = p0 + p1;
#pragma unroll
            for (int o = 8; o > 0; o >>= 1)
                rs += __shfl_xor_sync(0xffffffffu, rs, o);
            float sc = __expf(mrow[i] - mn);
            mrow[i] = mn;
            lsum[i] = lsum[i] * sc + rs;
#pragma unroll
            for (int j = 0; j < 4; j++) O[i][j] *= sc;
            Ps[(ty << 2) + i][2 * tx]     = p0;
            Ps[(ty << 2) + i][2 * tx + 1] = p1;
        }
        __syncthreads();
        // O += P V : rows 4ty..+3, dims 4tx..+3
#pragma unroll 4
        for (int kk = 0; kk < 32; kk++) {
            float4 vv = *(const float4*)&Vs[kk][tx << 2];
            float vb[4] = {vv.x, vv.y, vv.z, vv.w};
#pragma unroll
            for (int i = 0; i < 4; i++) {
                float p = Ps[(ty << 2) + i][kk];
#pragma unroll
                for (int j = 0; j < 4; j++) O[i][j] += p * vb[j];
            }
        }
    }
    // normalize + write attn[t][h*64+d]
#pragma unroll
    for (int i = 0; i < 4; i++) {
        float inv = 1.f / lsum[i];
        int t = q0 + (ty << 2) + i;
#pragma unroll
        for (int j = 0; j < 4; j++)
            outp[(size_t)t * HDIM + h * 64 + (tx << 2) + j] = O[i][j] * inv;
    }
}

// ---------------- router: one warp per token ---------------------------------
__global__ __launch_bounds__(256)
void zero_cnt_kernel() { if (threadIdx.x < E_NUM) g_cnt[threadIdx.x] = 0; }

__global__ __launch_bounds__(256)
void router_kernel(const float* __restrict__ hn2, const float* __restrict__ rw)
{
    int warp = threadIdx.x >> 5, lane = threadIdx.x & 31;
    int t = blockIdx.x * 8 + warp;
    const float* xr = hn2 + (size_t)t * HDIM;
    float logit[E_NUM];
#pragma unroll
    for (int e = 0; e < E_NUM; e++) {
        const float* wr = rw + e * HDIM;
        float s = 0.f;
        for (int i = lane; i < HDIM; i += 32) s += xr[i] * wr[i];
#pragma unroll
        for (int o = 16; o > 0; o >>= 1) s += __shfl_xor_sync(0xffffffffu, s, o);
        logit[e] = s;
    }
    if (lane == 0) {
        float mx = logit[0];
#pragma unroll
        for (int e = 1; e < E_NUM; e++) mx = fmaxf(mx, logit[e]);
        float p[E_NUM], den = 0.f;
#pragma unroll
        for (int e = 0; e < E_NUM; e++) { p[e] = __expf(logit[e] - mx); den += p[e]; }
        float id = 1.f / den;
#pragma unroll
        for (int e = 0; e < E_NUM; e++) p[e] *= id;
        // top-2 on logits (tie -> smaller index, matching lax.top_k)
        int i1 = 0;
#pragma unroll
        for (int e = 1; e < E_NUM; e++) if (logit[e] > logit[i1]) i1 = e;
        int i2 = (i1 == 0) ? 1 : 0;
#pragma unroll
        for (int e = 0; e < E_NUM; e++)
            if (e != i1 && logit[e] > logit[i2]) i2 = e;
        int sl1 = atomicAdd(&g_cnt[i1], 1);
        g_list[(i1 << 11) + sl1] = t; g_gate[(i1 << 11) + sl1] = p[i1];
        g_slots[2 * t] = (i1 << 11) + sl1;
        int sl2 = atomicAdd(&g_cnt[i2], 1);
        g_list[(i2 << 11) + sl2] = t; g_gate[(i2 << 11) + sl2] = p[i2];
        g_slots[2 * t + 1] = (i2 << 11) + sl2;
    }
}

// ---------------- expert GEMM1: hmid = gate * gelu(X_e @ w1[e]) --------------
// grid.x = E*32 (expert, m-tile), grid.y = F/64. NN GEMM with gathered A rows.
__global__ __launch_bounds__(256)
void moe_gemm1(const float* __restrict__ hn2, const float* __restrict__ w1)
{
    int e = blockIdx.x >> 5;
    int m0 = (blockIdx.x & 31) << 6;
    int cnt = g_cnt[e];
    if (m0 >= cnt) return;
    int n0 = blockIdx.y << 6;
    const float* B = w1 + (size_t)e * HDIM * F_DIM;
    __shared__ float As[16][68];
    __shared__ float Bs[16][68];
    int tid = threadIdx.x, ty = tid >> 4, tx = tid & 15;
    int lrow = tid >> 2, lk4 = (tid & 3) << 2;
    int arow = m0 + lrow;
    int tok = g_list[(e << 11) + (arow < cnt ? arow : cnt - 1)];
    const float* Ap = hn2 + (size_t)tok * HDIM + lk4;
    int brow = tid >> 4, bcol = (tid & 15) << 2;
    const float* Bp = B + (size_t)brow * F_DIM + n0 + bcol;
    float acc[4][4] = {};
    for (int k0 = 0; k0 < HDIM; k0 += 16) {
        float4 a = *(const float4*)(Ap + k0);
        As[lk4 + 0][lrow] = a.x; As[lk4 + 1][lrow] = a.y;
        As[lk4 + 2][lrow] = a.z; As[lk4 + 3][lrow] = a.w;
        float4 b = *(const float4*)(Bp + (size_t)k0 * F_DIM);
        *(float4*)&Bs[brow][bcol] = b;
        __syncthreads();
#pragma unroll
        for (int kk = 0; kk < 16; kk++) {
            float4 av = *(const float4*)&As[kk][ty << 2];
            float4 bv = *(const float4*)&Bs[kk][tx << 2];
            float aa[4] = {av.x, av.y, av.z, av.w};
            float bb[4] = {bv.x, bv.y, bv.z, bv.w};
#pragma unroll
            for (int i = 0; i < 4; i++)
#pragma unroll
                for (int j = 0; j < 4; j++) acc[i][j] += aa[i] * bb[j];
        }
        __syncthreads();
    }
#pragma unroll
    for (int i = 0; i < 4; i++) {
        int m = m0 + (ty << 2) + i;
        if (m < cnt) {
            float g = g_gate[(e << 11) + m];
#pragma unroll
            for (int j = 0; j < 4; j++) {
                float v = acc[i][j];
                v = 0.5f * v * (1.f + erff(v * 0.70710678f));   // exact GELU
                g_hmid[((size_t)(e << 11) + m) * F_DIM + n0 + (tx << 2) + j] = v * g;
            }
        }
    }
}

// ---------------- expert GEMM2: ypair = hmid_e @ w2[e] -----------------------
__global__ __launch_bounds__(256)
void moe_gemm2(const float* __restrict__ w2)
{
    int e = blockIdx.x >> 5;
    int m0 = (blockIdx.x & 31) << 6;
    int cnt = g_cnt[e];
    if (m0 >= cnt) return;
    int n0 = blockIdx.y << 6;
    const float* B = w2 + (size_t)e * F_DIM * HDIM;
    __shared__ float As[16][68];
    __shared__ float Bs[16][68];
    int tid = threadIdx.x, ty = tid >> 4, tx = tid & 15;
    int lrow = tid >> 2, lk4 = (tid & 3) << 2;
    const float* Ap = g_hmid + ((size_t)(e << 11) + m0 + lrow) * F_DIM + lk4;
    int brow = tid >> 4, bcol = (tid & 15) << 2;
    const float* Bp = B + (size_t)brow * HDIM + n0 + bcol;
    float acc[4][4] = {};
    for (int k0 = 0; k0 < F_DIM; k0 += 16) {
        float4 a = *(const float4*)(Ap + k0);
        As[lk4 + 0][lrow] = a.x; As[lk4 + 1][lrow] = a.y;
        As[lk4 + 2][lrow] = a.z; As[lk4 + 3][lrow] = a.w;
        float4 b = *(const float4*)(Bp + (size_t)k0 * HDIM);
        *(float4*)&Bs[brow][bcol] = b;
        __syncthreads();
#pragma unroll
        for (int kk = 0; kk < 16; kk++) {
            float4 av = *(const float4*)&As[kk][ty << 2];
            float4 bv = *(const float4*)&Bs[kk][tx << 2];
            float aa[4] = {av.x, av.y, av.z, av.w};
            float bb[4] = {bv.x, bv.y, bv.z, bv.w};
#pragma unroll
            for (int i = 0; i < 4; i++)
#pragma unroll
                for (int j = 0; j < 4; j++) acc[i][j] += aa[i] * bb[j];
        }
        __syncthreads();
    }
#pragma unroll
    for (int i = 0; i < 4; i++) {
        int m = m0 + (ty << 2) + i;
        if (m < cnt) {
#pragma unroll
            for (int j = 0; j < 4; j++)
                g_ypair[((size_t)(e << 11) + m) * HDIM + n0 + (tx << 2) + j] = acc[i][j];
        }
    }
}

// ---------------- final combine: out = x1 + y(top1) + y(top2) ----------------
__global__ __launch_bounds__(256)
void final_add(float* __restrict__ out)
{
    int t = blockIdx.x;
    int s0 = g_slots[2 * t], s1 = g_slots[2 * t + 1];
    const float* y0 = g_ypair + (size_t)s0 * HDIM;
    const float* y1 = g_ypair + (size_t)s1 * HDIM;
    float* o = out + (size_t)t * HDIM;
#pragma unroll
    for (int i = 0; i < 4; i++) {
        int hh = threadIdx.x + (i << 8);
        o[hh] += y0[hh] + y1[hh];
    }
}

// ---------------- launch -----------------------------------------------------
extern "C" void kernel_launch(void* const* d_in, const int* in_sizes, int n_in,
                              void* d_out, int out_size)
{
    const float* x          = (const float*)d_in[0];
    const float* ln1_w      = (const float*)d_in[1];
    const float* ln1_b      = (const float*)d_in[2];
    const float* in_proj_w  = (const float*)d_in[3];
    const float* in_proj_b  = (const float*)d_in[4];
    const float* out_proj_w = (const float*)d_in[5];
    const float* out_proj_b = (const float*)d_in[6];
    const float* ln2_w      = (const float*)d_in[7];
    const float* ln2_b      = (const float*)d_in[8];
    const float* router_w   = (const float*)d_in[9];
    const float* w1         = (const float*)d_in[10];
    const float* w2         = (const float*)d_in[11];
    float* out = (float*)d_out;

    float *p_hn, *p_qkv, *p_attn, *p_hn2;
    cudaGetSymbolAddress((void**)&p_hn,   g_hn);
    cudaGetSymbolAddress((void**)&p_qkv,  g_qkv);
    cudaGetSymbolAddress((void**)&p_attn, g_attn);
    cudaGetSymbolAddress((void**)&p_hn2,  g_hn2);

    // 1) ln1
    ln_kernel<<<S_LEN, 256>>>(x, ln1_w, ln1_b, p_hn);
    // 2) qkv = hn @ in_proj_w^T + b   [2048 x 3072]
    gemm_nt<<<dim3(S_LEN / 64, 3 * HDIM / 64), 256>>>(
        p_hn, in_proj_w, in_proj_b, nullptr, p_qkv, S_LEN, 3 * HDIM, HDIM);
    // 3) flash attention
    attn_kernel<<<dim3(S_LEN / 64, NH), 256>>>(p_qkv, p_attn);
    // 4) x1 = x + attn @ out_proj_w^T + b  -> written into d_out
    gemm_nt<<<dim3(S_LEN / 64, HDIM / 64), 256>>>(
        p_attn, out_proj_w, out_proj_b, x, out, S_LEN, HDIM, HDIM);
    // 5) ln2
    ln_kernel<<<S_LEN, 256>>>(out, ln2_w, ln2_b, p_hn2);
    // 6) router + top-2 gather
    zero_cnt_kernel<<<1, 256>>>();
    router_kernel<<<S_LEN / 8, 256>>>(p_hn2, router_w);
    // 7) expert GEMM1 (+gelu, +gate)
    moe_gemm1<<<dim3(E_NUM * (S_LEN / 64), F_DIM / 64), 256>>>(p_hn2, w1);
    // 8) expert GEMM2
    moe_gemm2<<<dim3(E_NUM * (S_LEN / 64), HDIM / 64), 256>>>(w2);
    // 9) out = x1 + gathered expert outputs
    final_add<<<S_LEN, 256>>>(out);
}

// round 2
// speedup vs baseline: 1.6933x; 1.6933x over previous
#include <cuda_runtime.h>
#include <math.h>
#include <stdint.h>

// Problem constants
#define S_LEN 2048
#define HDIM  1024
#define NH    16
#define HD    64
#define E_NUM 8
#define F_DIM 2048

#define BM 128
#define BN 128
#define BK 16

// ---------------- scratch (device globals; no allocations allowed) ----------
__device__ float g_hn  [S_LEN * HDIM];
__device__ float g_qkv [S_LEN * 3 * HDIM];
__device__ float g_attn[S_LEN * HDIM];
__device__ float g_hn2 [S_LEN * HDIM];
__device__ float g_hmid[(size_t)E_NUM * S_LEN * F_DIM];
__device__ float g_ypair[(size_t)E_NUM * S_LEN * HDIM];
__device__ int   g_cnt [E_NUM];
__device__ int   g_list[E_NUM * S_LEN];
__device__ float g_gate[E_NUM * S_LEN];
__device__ int   g_slots[S_LEN * 2];

// ---------------- helpers ----------------------------------------------------
__device__ __forceinline__ uint32_t f2t(float x)
{
    uint32_t r;
    asm("cvt.rna.tf32.f32 %0, %1;" : "=r"(r) : "f"(x));
    return r;
}

__device__ __forceinline__ void mma8(float* c, const uint32_t* a, const uint32_t* b)
{
    asm volatile(
        "mma.sync.aligned.m16n8k8.row.col.f32.tf32.tf32.f32 "
        "{%0,%1,%2,%3}, {%4,%5,%6,%7}, {%8,%9}, {%0,%1,%2,%3};"
        : "+f"(c[0]), "+f"(c[1]), "+f"(c[2]), "+f"(c[3])
        : "r"(a[0]), "r"(a[1]), "r"(a[2]), "r"(a[3]), "r"(b[0]), "r"(b[1]));
}

// ---------------- tf32 tensor-core GEMM --------------------------------------
// MODE 0: C = A @ B^T + bias                 (B is [N][K])      -> qkv
// MODE 1: C = A @ B^T + bias + res           (B is [N][K])      -> out-proj
// MODE 2: hmid = gate * gelu(gatherA @ B)    (B is [K][N], NN)  -> moe gemm1
// MODE 3: ypair = A_seg @ B                  (B is [K][N], NN)  -> moe gemm2
template<int MODE>
__global__ __launch_bounds__(256)
void tc_gemm(const float* __restrict__ A, const float* __restrict__ B,
             const float* __restrict__ bias, const float* __restrict__ res,
             float* __restrict__ C, int M, int N, int K)
{
    __shared__ uint32_t As[BK][136];
    __shared__ uint32_t Bs[BK][136];

    int tid = threadIdx.x;
    int seg = 0, cnt = 0, m0, n0;
    if (MODE >= 2) {
        int e  = blockIdx.x >> 4;
        int mt = blockIdx.x & 15;
        cnt = g_cnt[e];
        m0  = mt * BM;
        if (m0 >= cnt) return;
        seg = e << 11;
        B += (size_t)e * K * N;   // per-expert weight slab
    } else {
        m0 = blockIdx.x * BM;
    }
    n0 = blockIdx.y * BN;

    // ---- global load mapping ----
    int rowA = tid & 127;
    int c4   = (tid >> 7) * 4;   // 0 or 4 : cols {c4..c4+3, c4+8..c4+11}
    const float* Apt;
    if (MODE == 2) {
        int rm  = m0 + rowA;
        int idx = rm < cnt ? rm : cnt - 1;
        Apt = A + (size_t)g_list[seg + idx] * K + c4;
    } else if (MODE == 3) {
        Apt = A + ((size_t)seg + m0 + rowA) * K + c4;
    } else {
        Apt = A + (size_t)(m0 + rowA) * K + c4;
    }
    const float* Bpt;
    int kB = 0, nB = 0;
    if (MODE <= 1) {
        Bpt = B + (size_t)(n0 + rowA) * K + c4;      // NT: row over N
    } else {
        kB  = tid >> 4;                              // 0..15
        nB  = (tid & 15) * 4;                        // 0..60
        Bpt = B + (size_t)kB * N + n0 + nB;
    }

    float acc[4][4][4] = {};
    int lane = tid & 31, wid = tid >> 5;
    int wm = (wid >> 2) * 64;    // warp M offset (0/64)
    int wn = (wid & 3) * 32;     // warp N offset (0/32/64/96)
    int lr = lane >> 2, lc = lane & 3;

    // prologue: load k-tile 0 into registers
    float4 pa0 = *(const float4*)(Apt);
    float4 pa1 = *(const float4*)(Apt + 8);
    float4 pb0, pb1;
    if (MODE <= 1) { pb0 = *(const float4*)(Bpt); pb1 = *(const float4*)(Bpt + 8); }
    else           { pb0 = *(const float4*)(Bpt); pb1 = *(const float4*)(Bpt + 64); }

    const int KT = K / BK;
    for (int kt = 0; kt < KT; kt++) {
        // ---- store staged tile to smem (convert to tf32) ----
        {
            float av[8] = {pa0.x, pa0.y, pa0.z, pa0.w, pa1.x, pa1.y, pa1.z, pa1.w};
#pragma unroll
            for (int v = 0; v < 4; v++) {
                As[c4 + v][rowA]     = f2t(av[v]);
                As[c4 + 8 + v][rowA] = f2t(av[4 + v]);
            }
            if (MODE <= 1) {
                float bv[8] = {pb0.x, pb0.y, pb0.z, pb0.w, pb1.x, pb1.y, pb1.z, pb1.w};
#pragma unroll
                for (int v = 0; v < 4; v++) {
                    Bs[c4 + v][rowA]     = f2t(bv[v]);
                    Bs[c4 + 8 + v][rowA] = f2t(bv[4 + v]);
                }
            } else {
                uint4 u0 = {f2t(pb0.x), f2t(pb0.y), f2t(pb0.z), f2t(pb0.w)};
                uint4 u1 = {f2t(pb1.x), f2t(pb1.y), f2t(pb1.z), f2t(pb1.w)};
                *(uint4*)&Bs[kB][nB]      = u0;
                *(uint4*)&Bs[kB][nB + 64] = u1;
            }
        }
        __syncthreads();

        // ---- prefetch next k-tile ----
        if (kt + 1 < KT) {
            const float* An = Apt + (kt + 1) * BK;
            pa0 = *(const float4*)(An);
            pa1 = *(const float4*)(An + 8);
            if (MODE <= 1) {
                const float* Bn = Bpt + (kt + 1) * BK;
                pb0 = *(const float4*)(Bn);
                pb1 = *(const float4*)(Bn + 8);
            } else {
                const float* Bn = Bpt + (size_t)(kt + 1) * BK * N;
                pb0 = *(const float4*)(Bn);
                pb1 = *(const float4*)(Bn + 64);
            }
        }

        // ---- compute 2 x k8 ----
#pragma unroll
        for (int ks = 0; ks < 2; ks++) {
            int ko = ks * 8;
            uint32_t a[4][4], b[4][2];
#pragma unroll
            for (int i = 0; i < 4; i++) {
                int r = wm + i * 16 + lr;
                a[i][0] = As[ko + lc][r];
                a[i][1] = As[ko + lc][r + 8];
                a[i][2] = As[ko + lc + 4][r];
                a[i][3] = As[ko + lc + 4][r + 8];
            }
#pragma unroll
            for (int j = 0; j < 4; j++) {
                int cN = wn + j * 8 + lr;
                b[j][0] = Bs[ko + lc][cN];
                b[j][1] = Bs[ko + lc + 4][cN];
            }
#pragma unroll
            for (int i = 0; i < 4; i++)
#pragma unroll
                for (int j = 0; j < 4; j++)
                    mma8(acc[i][j], a[i], b[j]);
        }
        __syncthreads();
    }

    // ---- epilogue ----
#pragma unroll
    for (int i = 0; i < 4; i++) {
#pragma unroll
        for (int s = 0; s < 2; s++) {
            int mloc = m0 + wm + i * 16 + lr + s * 8;     // row in tile-space
#pragma unroll
            for (int j = 0; j < 4; j++) {
                int cn = n0 + wn + j * 8 + 2 * lc;
                float v0 = acc[i][j][s * 2 + 0];
                float v1 = acc[i][j][s * 2 + 1];
                if (MODE <= 1) {
                    v0 += bias[cn]; v1 += bias[cn + 1];
                    if (MODE == 1) {
                        v0 += res[(size_t)mloc * N + cn];
                        v1 += res[(size_t)mloc * N + cn + 1];
                    }
                    *(float2*)&C[(size_t)mloc * N + cn] = make_float2(v0, v1);
                } else if (mloc < cnt) {
                    if (MODE == 2) {
                        float g = g_gate[seg + mloc];
                        v0 = 0.5f * v0 * (1.f + erff(v0 * 0.70710678f)) * g;
                        v1 = 0.5f * v1 * (1.f + erff(v1 * 0.70710678f)) * g;
                        *(float2*)&C[((size_t)seg + mloc) * N + cn] = make_float2(v0, v1);
                    } else {
                        *(float2*)&C[((size_t)seg + mloc) * N + cn] = make_float2(v0, v1);
                    }
                }
            }
        }
    }
}

// ---------------- layernorm: one block per row -------------------------------
__global__ __launch_bounds__(256)
void ln_kernel(const float* __restrict__ x, const float* __restrict__ w,
               const float* __restrict__ b, float* __restrict__ out)
{
    int t = blockIdx.x;
    const float* xr = x + (size_t)t * HDIM;
    float v[4];
    float s = 0.f, s2 = 0.f;
#pragma unroll
    for (int i = 0; i < 4; i++) {
        v[i] = xr[threadIdx.x + (i << 8)];
        s += v[i]; s2 += v[i] * v[i];
    }
#pragma unroll
    for (int o = 16; o > 0; o >>= 1) {
        s  += __shfl_xor_sync(0xffffffffu, s,  o);
        s2 += __shfl_xor_sync(0xffffffffu, s2, o);
    }
    __shared__ float red[2][8];
    int wid = threadIdx.x >> 5, lane = threadIdx.x & 31;
    if (lane == 0) { red[0][wid] = s; red[1][wid] = s2; }
    __syncthreads();
    float ts = 0.f, ts2 = 0.f;
#pragma unroll
    for (int i = 0; i < 8; i++) { ts += red[0][i]; ts2 += red[1][i]; }
    float mu   = ts * (1.f / HDIM);
    float var  = ts2 * (1.f / HDIM) - mu * mu;
    float rstd = rsqrtf(var + 1e-5f);
    float* orow = out + (size_t)t * HDIM;
#pragma unroll
    for (int i = 0; i < 4; i++) {
        int hh = threadIdx.x + (i << 8);
        orow[hh] = (v[i] - mu) * rstd * w[hh] + b[hh];
    }
}

// ---------------- flash attention: block = (64 queries, 1 head) --------------
__global__ __launch_bounds__(256)
void attn_kernel(const float* __restrict__ qkv, float* __restrict__ outp)
{
    __shared__ float Qs [64][68];
    __shared__ float Kst[64][36];
    __shared__ float Vs [32][68];
    __shared__ float Ps [64][36];
    int q0 = blockIdx.x << 6;
    int h  = blockIdx.y;
    int tid = threadIdx.x, ty = tid >> 4, tx = tid & 15;

#pragma unroll
    for (int r = 0; r < 4; r++) {
        int s = tid + (r << 8);
        int row = s >> 4, c4 = (s & 15) << 2;
        float4 q = *(const float4*)&qkv[(size_t)(q0 + row) * 3072 + h * 64 + c4];
        Qs[row][c4 + 0] = q.x * 0.125f; Qs[row][c4 + 1] = q.y * 0.125f;
        Qs[row][c4 + 2] = q.z * 0.125f; Qs[row][c4 + 3] = q.w * 0.125f;
    }

    float O[4][4] = {};
    float mrow[4], lsum[4];
#pragma unroll
    for (int i = 0; i < 4; i++) { mrow[i] = -1e30f; lsum[i] = 0.f; }

    int ntiles = (q0 >> 5) + 2;
    for (int jt = 0; jt < ntiles; jt++) {
        int k0 = jt << 5;
        __syncthreads();
#pragma unroll
        for (int r = 0; r < 2; r++) {
            int s = tid + (r << 8);
            int row = s >> 4, c4 = (s & 15) << 2;
            const float* base = &qkv[(size_t)(k0 + row) * 3072 + h * 64 + c4];
            float4 kv = *(const float4*)(base + 1024);
            Kst[c4 + 0][row] = kv.x; Kst[c4 + 1][row] = kv.y;
            Kst[c4 + 2][row] = kv.z; Kst[c4 + 3][row] = kv.w;
            float4 vv = *(const float4*)(base + 2048);
            *(float4*)&Vs[row][c4] = vv;
        }
        __syncthreads();

        float sv[4][2];
#pragma unroll
        for (int i = 0; i < 4; i++) { sv[i][0] = 0.f; sv[i][1] = 0.f; }
#pragma unroll 8
        for (int kk = 0; kk < 64; kk++) {
            float b0 = Kst[kk][2 * tx], b1 = Kst[kk][2 * tx + 1];
#pragma unroll
            for (int i = 0; i < 4; i++) {
                float a = Qs[(ty << 2) + i][kk];
                sv[i][0] += a * b0; sv[i][1] += a * b1;
            }
        }
#pragma unroll
        for (int i = 0; i < 4; i++) {
            int qrow = q0 + (ty << 2) + i;
            float s0 = (k0 + 2 * tx     <= qrow) ? sv[i][0] : -1e30f;
            float s1 = (k0 + 2 * tx + 1 <= qrow) ? sv[i][1] : -1e30f;
            float rm = fmaxf(s0, s1);
#pragma unroll
            for (int o = 8; o > 0; o >>= 1)
                rm = fmaxf(rm, __shfl_xor_sync(0xffffffffu, rm, o));
            float mn = fmaxf(mrow[i], rm);
            float p0 = __expf(s0 - mn), p1 = __expf(s1 - mn);
            float rs = p0 + p1;
#pragma unroll
            for (int o = 8; o > 0; o >>= 1)
                rs += __shfl_xor_sync(0xffffffffu, rs, o);
            float sc = __expf(mrow[i] - mn);
            mrow[i] = mn;
            lsum[i] = lsum[i] * sc + rs;
#pragma unroll
            for (int j = 0; j < 4; j++) O[i][j] *= sc;
            Ps[(ty << 2) + i][2 * tx]     = p0;
            Ps[(ty << 2) + i][2 * tx + 1] = p1;
        }
        __syncthreads();
#pragma unroll 4
        for (int kk = 0; kk < 32; kk++) {
            float4 vv = *(const float4*)&Vs[kk][tx << 2];
            float vb[4] = {vv.x, vv.y, vv.z, vv.w};
#pragma unroll
            for (int i = 0; i < 4; i++) {
                float p = Ps[(ty << 2) + i][kk];
#pragma unroll
                for (int j = 0; j < 4; j++) O[i][j] += p * vb[j];
            }
        }
    }
#pragma unroll
    for (int i = 0; i < 4; i++) {
        float inv = 1.f / lsum[i];
        int t = q0 + (ty << 2) + i;
#pragma unroll
        for (int j = 0; j < 4; j++)
            outp[(size_t)t * HDIM + h * 64 + (tx << 2) + j] = O[i][j] * inv;
    }
}

// ---------------- router ------------------------------------------------------
__global__ __launch_bounds__(256)
void zero_cnt_kernel() { if (threadIdx.x < E_NUM) g_cnt[threadIdx.x] = 0; }

__global__ __launch_bounds__(256)
void router_kernel(const float* __restrict__ hn2, const float* __restrict__ rw)
{
    int warp = threadIdx.x >> 5, lane = threadIdx.x & 31;
    int t = blockIdx.x * 8 + warp;
    const float* xr = hn2 + (size_t)t * HDIM;
    float logit[E_NUM];
#pragma unroll
    for (int e = 0; e < E_NUM; e++) {
        const float* wr = rw + e * HDIM;
        float s = 0.f;
        for (int i = lane; i < HDIM; i += 32) s += xr[i] * wr[i];
#pragma unroll
        for (int o = 16; o > 0; o >>= 1) s += __shfl_xor_sync(0xffffffffu, s, o);
        logit[e] = s;
    }
    if (lane == 0) {
        float mx = logit[0];
#pragma unroll
        for (int e = 1; e < E_NUM; e++) mx = fmaxf(mx, logit[e]);
        float p[E_NUM], den = 0.f;
#pragma unroll
        for (int e = 0; e < E_NUM; e++) { p[e] = __expf(logit[e] - mx); den += p[e]; }
        float id = 1.f / den;
#pragma unroll
        for (int e = 0; e < E_NUM; e++) p[e] *= id;
        int i1 = 0;
#pragma unroll
        for (int e = 1; e < E_NUM; e++) if (logit[e] > logit[i1]) i1 = e;
        int i2 = (i1 == 0) ? 1 : 0;
#pragma unroll
        for (int e = 0; e < E_NUM; e++)
            if (e != i1 && logit[e] > logit[i2]) i2 = e;
        int sl1 = atomicAdd(&g_cnt[i1], 1);
        g_list[(i1 << 11) + sl1] = t; g_gate[(i1 << 11) + sl1] = p[i1];
        g_slots[2 * t] = (i1 << 11) + sl1;
        int sl2 = atomicAdd(&g_cnt[i2], 1);
        g_list[(i2 << 11) + sl2] = t; g_gate[(i2 << 11) + sl2] = p[i2];
        g_slots[2 * t + 1] = (i2 << 11) + sl2;
    }
}

// ---------------- final combine ----------------------------------------------
__global__ __launch_bounds__(256)
void final_add(float* __restrict__ out)
{
    int t = blockIdx.x;
    int s0 = g_slots[2 * t], s1 = g_slots[2 * t + 1];
    const float* y0 = g_ypair + (size_t)s0 * HDIM;
    const float* y1 = g_ypair + (size_t)s1 * HDIM;
    float* o = out + (size_t)t * HDIM;
#pragma unroll
    for (int i = 0; i < 4; i++) {
        int hh = threadIdx.x + (i << 8);
        o[hh] += y0[hh] + y1[hh];
    }
}

// ---------------- launch -----------------------------------------------------
extern "C" void kernel_launch(void* const* d_in, const int* in_sizes, int n_in,
                              void* d_out, int out_size)
{
    const float* x          = (const float*)d_in[0];
    const float* ln1_w      = (const float*)d_in[1];
    const float* ln1_b      = (const float*)d_in[2];
    const float* in_proj_w  = (const float*)d_in[3];
    const float* in_proj_b  = (const float*)d_in[4];
    const float* out_proj_w = (const float*)d_in[5];
    const float* out_proj_b = (const float*)d_in[6];
    const float* ln2_w      = (const float*)d_in[7];
    const float* ln2_b      = (const float*)d_in[8];
    const float* router_w   = (const float*)d_in[9];
    const float* w1         = (const float*)d_in[10];
    const float* w2         = (const float*)d_in[11];
    float* out = (float*)d_out;

    float *p_hn, *p_qkv, *p_attn, *p_hn2, *p_hmid, *p_ypair;
    cudaGetSymbolAddress((void**)&p_hn,    g_hn);
    cudaGetSymbolAddress((void**)&p_qkv,   g_qkv);
    cudaGetSymbolAddress((void**)&p_attn,  g_attn);
    cudaGetSymbolAddress((void**)&p_hn2,   g_hn2);
    cudaGetSymbolAddress((void**)&p_hmid,  g_hmid);
    cudaGetSymbolAddress((void**)&p_ypair, g_ypair);

    // 1) ln1
    ln_kernel<<<S_LEN, 256>>>(x, ln1_w, ln1_b, p_hn);
    // 2) qkv = hn @ in_proj_w^T + b
    tc_gemm<0><<<dim3(S_LEN / BM, 3 * HDIM / BN), 256>>>(
        p_hn, in_proj_w, in_proj_b, nullptr, p_qkv, S_LEN, 3 * HDIM, HDIM);
    // 3) flash attention
    attn_kernel<<<dim3(S_LEN / 64, NH), 256>>>(p_qkv, p_attn);
    // 4) x1 = x + attn @ out_proj_w^T + b
    tc_gemm<1><<<dim3(S_LEN / BM, HDIM / BN), 256>>>(
        p_attn, out_proj_w, out_proj_b, x, out, S_LEN, HDIM, HDIM);
    // 5) ln2
    ln_kernel<<<S_LEN, 256>>>(out, ln2_w, ln2_b, p_hn2);
    // 6) router + top-2 gather
    zero_cnt_kernel<<<1, 256>>>();
    router_kernel<<<S_LEN / 8, 256>>>(p_hn2, router_w);
    // 7) expert GEMM1 (+gelu, +gate): NN, gather rows
    tc_gemm<2><<<dim3(E_NUM * (S_LEN / BM), F_DIM / BN), 256>>>(
        p_hn2, w1, nullptr, nullptr, p_hmid, S_LEN, F_DIM, HDIM);
    // 8) expert GEMM2: NN
    tc_gemm<3><<<dim3(E_NUM * (S_LEN / BM), HDIM / BN), 256>>>(
        p_hmid, w2, nullptr, nullptr, p_ypair, S_LEN, HDIM, F_DIM);
    // 9) out = x1 + gathered expert outputs
    final_add<<<S_LEN, 256>>>(out);
}

// round 3
// speedup vs baseline: 2.0299x; 1.1988x over previous
#include <cuda_runtime.h>
#include <math.h>
#include <stdint.h>

// Problem constants
#define S_LEN 2048
#define HDIM  1024
#define NH    16
#define HD    64
#define E_NUM 8
#define F_DIM 2048

#define BM 128
#define BN 128
#define BK 32

// ---------------- scratch (device globals; no allocations allowed) ----------
__device__ float g_hn  [S_LEN * HDIM];
__device__ float g_qkv [S_LEN * 3 * HDIM];
__device__ float g_attn[S_LEN * HDIM];
__device__ float g_hn2 [S_LEN * HDIM];
__device__ float g_hmid[(size_t)E_NUM * S_LEN * F_DIM];
__device__ float g_ypair[(size_t)E_NUM * S_LEN * HDIM];
__device__ int   g_cnt [E_NUM];
__device__ int   g_list[E_NUM * S_LEN];
__device__ float g_gate[E_NUM * S_LEN];
__device__ int   g_slots[S_LEN * 2];

// ---------------- helpers ----------------------------------------------------
__device__ __forceinline__ uint32_t pack2(float lo, float hi)
{
    uint32_t r;
    asm("cvt.rn.bf16x2.f32 %0, %1, %2;" : "=r"(r) : "f"(hi), "f"(lo));
    return r;
}

__device__ __forceinline__ void mma16(float* c, const uint32_t* a, const uint32_t* b)
{
    asm volatile(
        "mma.sync.aligned.m16n8k16.row.col.f32.bf16.bf16.f32 "
        "{%0,%1,%2,%3}, {%4,%5,%6,%7}, {%8,%9}, {%0,%1,%2,%3};"
        : "+f"(c[0]), "+f"(c[1]), "+f"(c[2]), "+f"(c[3])
        : "r"(a[0]), "r"(a[1]), "r"(a[2]), "r"(a[3]), "r"(b[0]), "r"(b[1]));
}

__device__ __forceinline__ void ldsm4(uint32_t& r0, uint32_t& r1, uint32_t& r2,
                                      uint32_t& r3, uint32_t addr)
{
    asm volatile("ldmatrix.sync.aligned.m8n8.x4.shared.b16 {%0,%1,%2,%3}, [%4];"
                 : "=r"(r0), "=r"(r1), "=r"(r2), "=r"(r3) : "r"(addr));
}

__device__ __forceinline__ void ldsm4t(uint32_t& r0, uint32_t& r1, uint32_t& r2,
                                       uint32_t& r3, uint32_t addr)
{
    asm volatile("ldmatrix.sync.aligned.m8n8.x4.trans.shared.b16 {%0,%1,%2,%3}, [%4];"
                 : "=r"(r0), "=r"(r1), "=r"(r2), "=r"(r3) : "r"(addr));
}

__device__ __forceinline__ uint32_t smaddr(const uint32_t* p)
{
    return (uint32_t)__cvta_generic_to_shared(p);
}

// ---------------- bf16 tensor-core GEMM --------------------------------------
// MODE 0: C = A @ B^T + bias                 (B is [N][K])      -> qkv
// MODE 1: C = A @ B^T + bias + res           (B is [N][K])      -> out-proj
// MODE 2: hmid = gate * gelu(gatherA @ B)    (B is [K][N], NN)  -> moe gemm1
// MODE 3: ypair = A_seg @ B                  (B is [K][N], NN)  -> moe gemm2
//
// Smem layouts (bf16, double buffered):
//   A  : [m 0..127][k 0..31], row stride 20 words (80B)  -> ldmatrix conflict-free
//   B NT: [n 0..127][k 0..31], row stride 20 words (80B)
//   B NN: [k 0..31][n 0..127], row stride 68 words (272B) -> ldmatrix.trans
template<int MODE>
__global__ __launch_bounds__(256)
void tc_gemm(const float* __restrict__ A, const float* __restrict__ B,
             const float* __restrict__ bias, const float* __restrict__ res,
             float* __restrict__ C, int M, int N, int K)
{
    __shared__ __align__(16) uint32_t sA[2][128 * 20];
    __shared__ __align__(16) uint32_t sB[2][128 * 20];   // NN uses 32*68 <= 2560

    int tid = threadIdx.x;
    int seg = 0, cnt = 0, m0, n0;
    if (MODE >= 2) {
        int e  = blockIdx.x >> 4;
        int mt = blockIdx.x & 15;
        cnt = g_cnt[e];
        m0  = mt * BM;
        if (m0 >= cnt) return;
        seg = e << 11;
        B += (size_t)e * K * N;
    } else {
        m0 = blockIdx.x * BM;
    }
    n0 = blockIdx.y * BN;

    // ---- global load mapping ----
    int rowA = tid & 127;
    int cW   = tid >> 7;                 // 0/1: k half
    const float* Apt;
    if (MODE == 2) {
        int rm  = m0 + rowA;
        int idx = rm < cnt ? rm : cnt - 1;
        Apt = A + (size_t)g_list[seg + idx] * K + cW * 16;
    } else if (MODE == 3) {
        Apt = A + ((size_t)seg + m0 + rowA) * K + cW * 16;
    } else {
        Apt = A + (size_t)(m0 + rowA) * K + cW * 16;
    }
    const float* Bpt;
    int kR = 0, nC = 0;
    if (MODE <= 1) {
        Bpt = B + (size_t)(n0 + rowA) * K + cW * 16;
    } else {
        kR  = tid >> 3;                  // 0..31
        nC  = (tid & 7) * 16;            // 0..112
        Bpt = B + (size_t)kR * N + n0 + nC;
    }
    int wA = rowA * 20 + cW * 8;                         // A sts word offset
    int wB = (MODE <= 1) ? wA : (kR * 68 + (tid & 7) * 8);

    float acc[4][4][4] = {};
    int lane = tid & 31, wid = tid >> 5;
    int wm = (wid >> 2) * 64;
    int wn = (wid & 3) * 32;
    int lr = lane >> 2, lc = lane & 3;

    // precomputed fragment smem addresses (word indices)
    int aw[4], bw0, bw1;
#pragma unroll
    for (int i = 0; i < 4; i++)
        aw[i] = (wm + i * 16 + (lane & 15)) * 20 + (lane >> 4) * 4;
    if (MODE <= 1) {
        bw0 = (wn + lane) * 20;          // +ks*8, +4 for second chunk
        bw1 = bw0 + 4;
    } else {
        bw0 = (((lane >> 3) & 1) * 8 + (lane & 7)) * 68
            + ((wn >> 3) + (lane >> 4)) * 4;             // +ks*16*68, +8 for gb=2
        bw1 = bw0 + 8;
    }

    const int KT = K / BK;
    float4 pa[4], pb[4];

    // ---- prologue: tile 0 ----
#pragma unroll
    for (int u = 0; u < 4; u++) pa[u] = *(const float4*)(Apt + u * 4);
    if (MODE <= 1) {
#pragma unroll
        for (int u = 0; u < 4; u++) pb[u] = *(const float4*)(Bpt + u * 4);
    } else {
#pragma unroll
        for (int u = 0; u < 4; u++) pb[u] = *(const float4*)(Bpt + u * 4);
    }
    {
        uint4 ua0 = {pack2(pa[0].x, pa[0].y), pack2(pa[0].z, pa[0].w),
                     pack2(pa[1].x, pa[1].y), pack2(pa[1].z, pa[1].w)};
        uint4 ua1 = {pack2(pa[2].x, pa[2].y), pack2(pa[2].z, pa[2].w),
                     pack2(pa[3].x, pa[3].y), pack2(pa[3].z, pa[3].w)};
        *(uint4*)&sA[0][wA]     = ua0;
        *(uint4*)&sA[0][wA + 4] = ua1;
        uint4 ub0 = {pack2(pb[0].x, pb[0].y), pack2(pb[0].z, pb[0].w),
                     pack2(pb[1].x, pb[1].y), pack2(pb[1].z, pb[1].w)};
        uint4 ub1 = {pack2(pb[2].x, pb[2].y), pack2(pb[2].z, pb[2].w),
                     pack2(pb[3].x, pb[3].y), pack2(pb[3].z, pb[3].w)};
        *(uint4*)&sB[0][wB]     = ub0;
        *(uint4*)&sB[0][wB + 4] = ub1;
    }
    __syncthreads();

    for (int kt = 0; kt < KT; kt++) {
        int buf = kt & 1;
        bool more = (kt + 1) < KT;
        // ---- prefetch next tile (LDG early) ----
        if (more) {
            const float* An = Apt + (kt + 1) * BK;
#pragma unroll
            for (int u = 0; u < 4; u++) pa[u] = *(const float4*)(An + u * 4);
            if (MODE <= 1) {
                const float* Bn = Bpt + (kt + 1) * BK;
#pragma unroll
                for (int u = 0; u < 4; u++) pb[u] = *(const float4*)(Bn + u * 4);
            } else {
                const float* Bn = Bpt + (size_t)(kt + 1) * BK * N;
#pragma unroll
                for (int u = 0; u < 4; u++) pb[u] = *(const float4*)(Bn + u * 4);
            }
        }

        // ---- compute from buf ----
        const uint32_t* sa = sA[buf];
        const uint32_t* sb = sB[buf];
#pragma unroll
        for (int ks = 0; ks < 2; ks++) {
            uint32_t a[4][4];
#pragma unroll
            for (int i = 0; i < 4; i++)
                ldsm4(a[i][0], a[i][1], a[i][2], a[i][3],
                      smaddr(&sa[aw[i] + ks * 8]));
            uint32_t b[4][2];
            if (MODE <= 1) {
                ldsm4(b[0][0], b[1][0], b[2][0], b[3][0],
                      smaddr(&sb[bw0 + ks * 8]));
                ldsm4(b[0][1], b[1][1], b[2][1], b[3][1],
                      smaddr(&sb[bw1 + ks * 8]));
            } else {
                ldsm4t(b[0][0], b[0][1], b[1][0], b[1][1],
                       smaddr(&sb[bw0 + ks * 16 * 68]));
                ldsm4t(b[2][0], b[2][1], b[3][0], b[3][1],
                       smaddr(&sb[bw1 + ks * 16 * 68]));
            }
#pragma unroll
            for (int i = 0; i < 4; i++)
#pragma unroll
                for (int j = 0; j < 4; j++)
                    mma16(acc[i][j], a[i], b[j]);
        }

        // ---- store prefetched tile into other buffer ----
        if (more) {
            int nb = buf ^ 1;
            uint4 ua0 = {pack2(pa[0].x, pa[0].y), pack2(pa[0].z, pa[0].w),
                         pack2(pa[1].x, pa[1].y), pack2(pa[1].z, pa[1].w)};
            uint4 ua1 = {pack2(pa[2].x, pa[2].y), pack2(pa[2].z, pa[2].w),
                         pack2(pa[3].x, pa[3].y), pack2(pa[3].z, pa[3].w)};
            *(uint4*)&sA[nb][wA]     = ua0;
            *(uint4*)&sA[nb][wA + 4] = ua1;
            uint4 ub0 = {pack2(pb[0].x, pb[0].y), pack2(pb[0].z, pb[0].w),
                         pack2(pb[1].x, pb[1].y), pack2(pb[1].z, pb[1].w)};
            uint4 ub1 = {pack2(pb[2].x, pb[2].y), pack2(pb[2].z, pb[2].w),
                         pack2(pb[3].x, pb[3].y), pack2(pb[3].z, pb[3].w)};
            *(uint4*)&sB[nb][wB]     = ub0;
            *(uint4*)&sB[nb][wB + 4] = ub1;
        }
        __syncthreads();
    }

    // ---- epilogue ----
#pragma unroll
    for (int i = 0; i < 4; i++) {
#pragma unroll
        for (int s = 0; s < 2; s++) {
            int mloc = m0 + wm + i * 16 + lr + s * 8;
#pragma unroll
            for (int j = 0; j < 4; j++) {
                int cn = n0 + wn + j * 8 + 2 * lc;
                float v0 = acc[i][j][s * 2 + 0];
                float v1 = acc[i][j][s * 2 + 1];
                if (MODE <= 1) {
                    v0 += bias[cn]; v1 += bias[cn + 1];
                    if (MODE == 1) {
                        v0 += res[(size_t)mloc * N + cn];
                        v1 += res[(size_t)mloc * N + cn + 1];
                    }
                    *(float2*)&C[(size_t)mloc * N + cn] = make_float2(v0, v1);
                } else if (mloc < cnt) {
                    if (MODE == 2) {
                        float g = g_gate[seg + mloc];
                        v0 = 0.5f * v0 * (1.f + erff(v0 * 0.70710678f)) * g;
                        v1 = 0.5f * v1 * (1.f + erff(v1 * 0.70710678f)) * g;
                    }
                    *(float2*)&C[((size_t)seg + mloc) * N + cn] = make_float2(v0, v1);
                }
            }
        }
    }
}

// ---------------- layernorm: one block per row -------------------------------
__global__ __launch_bounds__(256)
void ln_kernel(const float* __restrict__ x, const float* __restrict__ w,
               const float* __restrict__ b, float* __restrict__ out)
{
    int t = blockIdx.x;
    const float* xr = x + (size_t)t * HDIM;
    float v[4];
    float s = 0.f, s2 = 0.f;
#pragma unroll
    for (int i = 0; i < 4; i++) {
        v[i] = xr[threadIdx.x + (i << 8)];
        s += v[i]; s2 += v[i] * v[i];
    }
#pragma unroll
    for (int o = 16; o > 0; o >>= 1) {
        s  += __shfl_xor_sync(0xffffffffu, s,  o);
        s2 += __shfl_xor_sync(0xffffffffu, s2, o);
    }
    __shared__ float red[2][8];
    int wid = threadIdx.x >> 5, lane = threadIdx.x & 31;
    if (lane == 0) { red[0][wid] = s; red[1][wid] = s2; }
    __syncthreads();
    float ts = 0.f, ts2 = 0.f;
#pragma unroll
    for (int i = 0; i < 8; i++) { ts += red[0][i]; ts2 += red[1][i]; }
    float mu   = ts * (1.f / HDIM);
    float var  = ts2 * (1.f / HDIM) - mu * mu;
    float rstd = rsqrtf(var + 1e-5f);
    float* orow = out + (size_t)t * HDIM;
#pragma unroll
    for (int i = 0; i < 4; i++) {
        int hh = threadIdx.x + (i << 8);
        orow[hh] = (v[i] - mu) * rstd * w[hh] + b[hh];
    }
}

// ---------------- flash attention: block = (64 queries, 1 head) --------------
__global__ __launch_bounds__(256)
void attn_kernel(const float* __restrict__ qkv, float* __restrict__ outp)
{
    __shared__ float Qs [64][68];
    __shared__ float Kst[64][36];
    __shared__ float Vs [32][68];
    __shared__ float Ps [64][36];
    int q0 = blockIdx.x << 6;
    int h  = blockIdx.y;
    int tid = threadIdx.x, ty = tid >> 4, tx = tid & 15;

#pragma unroll
    for (int r = 0; r < 4; r++) {
        int s = tid + (r << 8);
        int row = s >> 4, c4 = (s & 15) << 2;
        float4 q = *(const float4*)&qkv[(size_t)(q0 + row) * 3072 + h * 64 + c4];
        Qs[row][c4 + 0] = q.x * 0.125f; Qs[row][c4 + 1] = q.y * 0.125f;
        Qs[row][c4 + 2] = q.z * 0.125f; Qs[row][c4 + 3] = q.w * 0.125f;
    }

    float O[4][4] = {};
    float mrow[4], lsum[4];
#pragma unroll
    for (int i = 0; i < 4; i++) { mrow[i] = -1e30f; lsum[i] = 0.f; }

    int ntiles = (q0 >> 5) + 2;
    for (int jt = 0; jt < ntiles; jt++) {
        int k0 = jt << 5;
        __syncthreads();
#pragma unroll
        for (int r = 0; r < 2; r++) {
            int s = tid + (r << 8);
            int row = s >> 4, c4 = (s & 15) << 2;
            const float* base = &qkv[(size_t)(k0 + row) * 3072 + h * 64 + c4];
            float4 kv = *(const float4*)(base + 1024);
            Kst[c4 + 0][row] = kv.x; Kst[c4 + 1][row] = kv.y;
            Kst[c4 + 2][row] = kv.z; Kst[c4 + 3][row] = kv.w;
            float4 vv = *(const float4*)(base + 2048);
            *(float4*)&Vs[row][c4] = vv;
        }
        __syncthreads();

        float sv[4][2];
#pragma unroll
        for (int i = 0; i < 4; i++) { sv[i][0] = 0.f; sv[i][1] = 0.f; }
#pragma unroll 8
        for (int kk = 0; kk < 64; kk++) {
            float b0 = Kst[kk][2 * tx], b1 = Kst[kk][2 * tx + 1];
#pragma unroll
            for (int i = 0; i < 4; i++) {
                float a = Qs[(ty << 2) + i][kk];
                sv[i][0] += a * b0; sv[i][1] += a * b1;
            }
        }
#pragma unroll
        for (int i = 0; i < 4; i++) {
            int qrow = q0 + (ty << 2) + i;
            float s0 = (k0 + 2 * tx     <= qrow) ? sv[i][0] : -1e30f;
            float s1 = (k0 + 2 * tx + 1 <= qrow) ? sv[i][1] : -1e30f;
            float rm = fmaxf(s0, s1);
#pragma unroll
            for (int o = 8; o > 0; o >>= 1)
                rm = fmaxf(rm, __shfl_xor_sync(0xffffffffu, rm, o));
            float mn = fmaxf(mrow[i], rm);
            float p0 = __expf(s0 - mn), p1 = __expf(s1 - mn);
            float rs = p0 + p1;
#pragma unroll
            for (int o = 8; o > 0; o >>= 1)
                rs += __shfl_xor_sync(0xffffffffu, rs, o);
            float sc = __expf(mrow[i] - mn);
            mrow[i] = mn;
            lsum[i] = lsum[i] * sc + rs;
#pragma unroll
            for (int j = 0; j < 4; j++) O[i][j] *= sc;
            Ps[(ty << 2) + i][2 * tx]     = p0;
            Ps[(ty << 2) + i][2 * tx + 1] = p1;
        }
        __syncthreads();
#pragma unroll 4
        for (int kk = 0; kk < 32; kk++) {
            float4 vv = *(const float4*)&Vs[kk][tx << 2];
            float vb[4] = {vv.x, vv.y, vv.z, vv.w};
#pragma unroll
            for (int i = 0; i < 4; i++) {
                float p = Ps[(ty << 2) + i][kk];
#pragma unroll
                for (int j = 0; j < 4; j++) O[i][j] += p * vb[j];
            }
        }
    }
#pragma unroll
    for (int i = 0; i < 4; i++) {
        float inv = 1.f / lsum[i];
        int t = q0 + (ty << 2) + i;
#pragma unroll
        for (int j = 0; j < 4; j++)
            outp[(size_t)t * HDIM + h * 64 + (tx << 2) + j] = O[i][j] * inv;
    }
}

// ---------------- router ------------------------------------------------------
__global__ __launch_bounds__(256)
void zero_cnt_kernel() { if (threadIdx.x < E_NUM) g_cnt[threadIdx.x] = 0; }

__global__ __launch_bounds__(256)
void router_kernel(const float* __restrict__ hn2, const float* __restrict__ rw)
{
    int warp = threadIdx.x >> 5, lane = threadIdx.x & 31;
    int t = blockIdx.x * 8 + warp;
    const float* xr = hn2 + (size_t)t * HDIM;
    float logit[E_NUM];
#pragma unroll
    for (int e = 0; e < E_NUM; e++) {
        const float* wr = rw + e * HDIM;
        float s = 0.f;
        for (int i = lane; i < HDIM; i += 32) s += xr[i] * wr[i];
#pragma unroll
        for (int o = 16; o > 0; o >>= 1) s += __shfl_xor_sync(0xffffffffu, s, o);
        logit[e] = s;
    }
    if (lane == 0) {
        float mx = logit[0];
#pragma unroll
        for (int e = 1; e < E_NUM; e++) mx = fmaxf(mx, logit[e]);
        float p[E_NUM], den = 0.f;
#pragma unroll
        for (int e = 0; e < E_NUM; e++) { p[e] = __expf(logit[e] - mx); den += p[e]; }
        float id = 1.f / den;
#pragma unroll
        for (int e = 0; e < E_NUM; e++) p[e] *= id;
        int i1 = 0;
#pragma unroll
        for (int e = 1; e < E_NUM; e++) if (logit[e] > logit[i1]) i1 = e;
        int i2 = (i1 == 0) ? 1 : 0;
#pragma unroll
        for (int e = 0; e < E_NUM; e++)
            if (e != i1 && logit[e] > logit[i2]) i2 = e;
        int sl1 = atomicAdd(&g_cnt[i1], 1);
        g_list[(i1 << 11) + sl1] = t; g_gate[(i1 << 11) + sl1] = p[i1];
        g_slots[2 * t] = (i1 << 11) + sl1;
        int sl2 = atomicAdd(&g_cnt[i2], 1);
        g_list[(i2 << 11) + sl2] = t; g_gate[(i2 << 11) + sl2] = p[i2];
        g_slots[2 * t + 1] = (i2 << 11) + sl2;
    }
}

// ---------------- final combine ----------------------------------------------
__global__ __launch_bounds__(256)
void final_add(float* __restrict__ out)
{
    int t = blockIdx.x;
    int s0 = g_slots[2 * t], s1 = g_slots[2 * t + 1];
    const float* y0 = g_ypair + (size_t)s0 * HDIM;
    const float* y1 = g_ypair + (size_t)s1 * HDIM;
    float* o = out + (size_t)t * HDIM;
#pragma unroll
    for (int i = 0; i < 4; i++) {
        int hh = threadIdx.x + (i << 8);
        o[hh] += y0[hh] + y1[hh];
    }
}

// ---------------- launch -----------------------------------------------------
extern "C" void kernel_launch(void* const* d_in, const int* in_sizes, int n_in,
                              void* d_out, int out_size)
{
    const float* x          = (const float*)d_in[0];
    const float* ln1_w      = (const float*)d_in[1];
    const float* ln1_b      = (const float*)d_in[2];
    const float* in_proj_w  = (const float*)d_in[3];
    const float* in_proj_b  = (const float*)d_in[4];
    const float* out_proj_w = (const float*)d_in[5];
    const float* out_proj_b = (const float*)d_in[6];
    const float* ln2_w      = (const float*)d_in[7];
    const float* ln2_b      = (const float*)d_in[8];
    const float* router_w   = (const float*)d_in[9];
    const float* w1         = (const float*)d_in[10];
    const float* w2         = (const float*)d_in[11];
    float* out = (float*)d_out;

    float *p_hn, *p_qkv, *p_attn, *p_hn2, *p_hmid, *p_ypair;
    cudaGetSymbolAddress((void**)&p_hn,    g_hn);
    cudaGetSymbolAddress((void**)&p_qkv,   g_qkv);
    cudaGetSymbolAddress((void**)&p_attn,  g_attn);
    cudaGetSymbolAddress((void**)&p_hn2,   g_hn2);
    cudaGetSymbolAddress((void**)&p_hmid,  g_hmid);
    cudaGetSymbolAddress((void**)&p_ypair, g_ypair);

    // 1) ln1
    ln_kernel<<<S_LEN, 256>>>(x, ln1_w, ln1_b, p_hn);
    // 2) qkv = hn @ in_proj_w^T + b
    tc_gemm<0><<<dim3(S_LEN / BM, 3 * HDIM / BN), 256>>>(
        p_hn, in_proj_w, in_proj_b, nullptr, p_qkv, S_LEN, 3 * HDIM, HDIM);
    // 3) flash attention
    attn_kernel<<<dim3(S_LEN / 64, NH), 256>>>(p_qkv, p_attn);
    // 4) x1 = x + attn @ out_proj_w^T + b
    tc_gemm<1><<<dim3(S_LEN / BM, HDIM / BN), 256>>>(
        p_attn, out_proj_w, out_proj_b, x, out, S_LEN, HDIM, HDIM);
    // 5) ln2
    ln_kernel<<<S_LEN, 256>>>(out, ln2_w, ln2_b, p_hn2);
    // 6) router + top-2 gather
    zero_cnt_kernel<<<1, 256>>>();
    router_kernel<<<S_LEN / 8, 256>>>(p_hn2, router_w);
    // 7) expert GEMM1 (+gelu, +gate): NN, gather rows
    tc_gemm<2><<<dim3(E_NUM * (S_LEN / BM), F_DIM / BN), 256>>>(
        p_hn2, w1, nullptr, nullptr, p_hmid, S_LEN, F_DIM, HDIM);
    // 8) expert GEMM2: NN
    tc_gemm<3><<<dim3(E_NUM * (S_LEN / BM), HDIM / BN), 256>>>(
        p_hmid, w2, nullptr, nullptr, p_ypair, S_LEN, HDIM, F_DIM);
    // 9) out = x1 + gathered expert outputs
    final_add<<<S_LEN, 256>>>(out);
}